// round 9
// baseline (speedup 1.0000x reference)
#include <cuda_runtime.h>
#include <cuda_bf16.h>
#include <math.h>
#include <stdint.h>

typedef unsigned long long ull;

#define N_NODES 10000
#define NQ      10048          // 157 * 64
#define E_EDGES 160000
#define D_IN    256
#define H1      128
#define H2      64
#define NPAD1   10112          // pad for gemm scratch (79*128)
#define FULLM   0xFFFFFFFFu

// ---------------- scratch (device globals) ----------------
__device__ float g_dis [N_NODES];
__device__ int   g_cnt [N_NODES];
__device__ int   g_off [N_NODES];
__device__ int   g_cur [N_NODES];
__device__ int   g_total;
__device__ int   g_smax;                         // max|z| as float bits
__device__ int   g_crow[E_EDGES];
__device__ float g_cw  [E_EDGES];
__device__ float g_hw1 [NPAD1 * H1];
__device__ float g_h1  [NPAD1 * H1];
__device__ float g_hw23[NPAD1 * H1];
__device__ float g_z   [N_NODES * H2];
__device__ __align__(16) char g_q[NQ * 128];     // per row: hi8[64] | lo8[64]

// ---------------- prep ----------------
__global__ void k_prep() {
    int i = blockIdx.x * 256 + threadIdx.x;
    if (i < N_NODES) { g_dis[i] = 1.0f; g_cnt[i] = 0; }
    if (i == 0) { g_total = 0; g_smax = 0; }
}

// ---------------- f32x2 inner product over a 32-K chunk ----------------
template<int TM>
__device__ __forceinline__ void mma32(const float* __restrict__ As,
                                      const float* __restrict__ Bs,
                                      int ty, int tx, ull (&acc)[TM][4]) {
#pragma unroll
    for (int k = 0; k < 32; k++) {
        ulonglong2 p0 = *reinterpret_cast<const ulonglong2*>(Bs + k * 132 + tx * 8);
        ulonglong2 p1 = *reinterpret_cast<const ulonglong2*>(Bs + k * 132 + tx * 8 + 4);
        ull b[4] = {p0.x, p0.y, p1.x, p1.y};
#pragma unroll
        for (int i = 0; i < TM; i++) {
            float a = As[(ty * TM + i) * 36 + k];
            ull ad;
            asm("mov.b64 %0, {%1, %1};" : "=l"(ad) : "f"(a));
#pragma unroll
            for (int jp = 0; jp < 4; jp++)
                asm("fma.rn.f32x2 %0, %1, %2, %0;" : "+l"(acc[i][jp]) : "l"(ad), "l"(b[jp]));
        }
    }
}

// ---------------- fused: degree-count edges (blocks 0..624) + GEMM1 ----------------
__global__ __launch_bounds__(256) void k_deg_gemm1(const int* __restrict__ ei,
                                                   const float* __restrict__ ew,
                                                   const float* __restrict__ x,
                                                   const float* __restrict__ W1) {
    __shared__ __align__(16) float As[32 * 36];
    __shared__ __align__(16) float Bs[32 * 132];
    if (blockIdx.x < 625) {
        int e = blockIdx.x * 256 + threadIdx.x;
        if (e < E_EDGES) {
            int c = ei[E_EDGES + e];
            atomicAdd(&g_dis[c], ew[e]);
            atomicAdd(&g_cnt[c], 1);
        }
        return;
    }
    int tid = threadIdx.x, tx = tid & 15, ty = tid >> 4;
    int mb = (blockIdx.x - 625) * 32;
    float4 pa, pb[4];
    {
        int m = tid >> 3, k4 = tid & 7;
        pa = make_float4(0.f, 0.f, 0.f, 0.f);
        if (mb + m < N_NODES)
            pa = *reinterpret_cast<const float4*>(x + (size_t)(mb + m) * D_IN + k4 * 4);
    }
#pragma unroll
    for (int r = 0; r < 4; r++) {
        int idx = tid + r * 256, kk = idx >> 5, n4 = idx & 31;
        pb[r] = *reinterpret_cast<const float4*>(W1 + (size_t)kk * H1 + n4 * 4);
    }
    ull acc[2][4] = {};
    for (int c = 0; c < 8; c++) {
        {
            int m = tid >> 3, k4 = tid & 7;
            *reinterpret_cast<float4*>(As + m * 36 + k4 * 4) = pa;
        }
#pragma unroll
        for (int r = 0; r < 4; r++) {
            int idx = tid + r * 256, kk = idx >> 5, n4 = idx & 31;
            *reinterpret_cast<float4*>(Bs + kk * 132 + n4 * 4) = pb[r];
        }
        __syncthreads();
        if (c < 7) {
            int kc = (c + 1) * 32;
            int m = tid >> 3, k4 = tid & 7;
            pa = make_float4(0.f, 0.f, 0.f, 0.f);
            if (mb + m < N_NODES)
                pa = *reinterpret_cast<const float4*>(x + (size_t)(mb + m) * D_IN + kc + k4 * 4);
#pragma unroll
            for (int r = 0; r < 4; r++) {
                int idx = tid + r * 256, kk = idx >> 5, n4 = idx & 31;
                pb[r] = *reinterpret_cast<const float4*>(W1 + (size_t)(kc + kk) * H1 + n4 * 4);
            }
        }
        mma32<2>(As, Bs, ty, tx, acc);
        __syncthreads();
    }
#pragma unroll
    for (int i = 0; i < 2; i++) {
        int row = mb + ty * 2 + i;
        float cv[8];
#pragma unroll
        for (int jp = 0; jp < 4; jp++)
            asm("mov.b64 {%0, %1}, %2;" : "=f"(cv[jp*2]), "=f"(cv[jp*2+1]) : "l"(acc[i][jp]));
        float4* p = reinterpret_cast<float4*>(g_hw1 + (size_t)row * H1 + tx * 8);
        p[0] = make_float4(cv[0], cv[1], cv[2], cv[3]);
        p[1] = make_float4(cv[4], cv[5], cv[6], cv[7]);
    }
}

// ---------------- offsets ----------------
__global__ void k_offsets() {
    __shared__ int s[256];
    __shared__ int sbase;
    int t = threadIdx.x;
    int i = blockIdx.x * 256 + t;
    int v = (i < N_NODES) ? g_cnt[i] : 0;
    s[t] = v; __syncthreads();
    for (int d = 1; d < 256; d <<= 1) {
        int x = (t >= d) ? s[t - d] : 0;
        __syncthreads();
        s[t] += x;
        __syncthreads();
    }
    if (t == 255) sbase = atomicAdd(&g_total, s[255]);
    __syncthreads();
    if (i < N_NODES) {
        int off = sbase + s[t] - v;
        g_off[i] = off; g_cur[i] = off;
        g_dis[i] = rsqrtf(g_dis[i]);
    }
}
__global__ void k_scatter(const int* __restrict__ ei, const float* __restrict__ ew) {
    int e = blockIdx.x * 256 + threadIdx.x;
    if (e < E_EDGES) {
        int r = ei[e], c = ei[E_EDGES + e];
        int p = atomicAdd(&g_cur[c], 1);
        g_crow[p] = r;
        g_cw[p]   = g_dis[r] * ew[e] * g_dis[c];
    }
}

// ---------------- GEMM23 ----------------
__global__ __launch_bounds__(256) void k_gemm23(const float* __restrict__ W2,
                                                const float* __restrict__ W3) {
    __shared__ __align__(16) float As[32 * 36];
    __shared__ __align__(16) float Bs[32 * 132];
    int tid = threadIdx.x, tx = tid & 15, ty = tid >> 4;
    int mb = blockIdx.x * 32;
    float4 pa, pb[4];
    {
        int m = tid >> 3, k4 = tid & 7;
        float4 v = *reinterpret_cast<const float4*>(g_h1 + (size_t)(mb + m) * H1 + k4 * 4);
        pa = make_float4(fmaxf(v.x, 0.f), fmaxf(v.y, 0.f), fmaxf(v.z, 0.f), fmaxf(v.w, 0.f));
    }
#pragma unroll
    for (int r = 0; r < 4; r++) {
        int idx = tid + r * 256, kk = idx >> 5, n4 = idx & 31;
        pb[r] = (n4 < 16)
            ? *reinterpret_cast<const float4*>(W2 + (size_t)kk * H2 + n4 * 4)
            : *reinterpret_cast<const float4*>(W3 + (size_t)kk * H2 + (n4 - 16) * 4);
    }
    ull acc[2][4] = {};
    for (int c = 0; c < 4; c++) {
        {
            int m = tid >> 3, k4 = tid & 7;
            *reinterpret_cast<float4*>(As + m * 36 + k4 * 4) = pa;
        }
#pragma unroll
        for (int r = 0; r < 4; r++) {
            int idx = tid + r * 256, kk = idx >> 5, n4 = idx & 31;
            *reinterpret_cast<float4*>(Bs + kk * 132 + n4 * 4) = pb[r];
        }
        __syncthreads();
        if (c < 3) {
            int kc = (c + 1) * 32;
            int m = tid >> 3, k4 = tid & 7;
            float4 v = *reinterpret_cast<const float4*>(g_h1 + (size_t)(mb + m) * H1 + kc + k4 * 4);
            pa = make_float4(fmaxf(v.x, 0.f), fmaxf(v.y, 0.f), fmaxf(v.z, 0.f), fmaxf(v.w, 0.f));
#pragma unroll
            for (int r = 0; r < 4; r++) {
                int idx = tid + r * 256, kk = idx >> 5, n4 = idx & 31;
                pb[r] = (n4 < 16)
                    ? *reinterpret_cast<const float4*>(W2 + (size_t)(kc + kk) * H2 + n4 * 4)
                    : *reinterpret_cast<const float4*>(W3 + (size_t)(kc + kk) * H2 + (n4 - 16) * 4);
            }
        }
        mma32<2>(As, Bs, ty, tx, acc);
        __syncthreads();
    }
#pragma unroll
    for (int i = 0; i < 2; i++) {
        int row = mb + ty * 2 + i;
        float cv[8];
#pragma unroll
        for (int jp = 0; jp < 4; jp++)
            asm("mov.b64 {%0, %1}, %2;" : "=f"(cv[jp*2]), "=f"(cv[jp*2+1]) : "l"(acc[i][jp]));
        float4* p = reinterpret_cast<float4*>(g_hw23 + (size_t)row * H1 + tx * 8);
        p[0] = make_float4(cv[0], cv[1], cv[2], cv[3]);
        p[1] = make_float4(cv[4], cv[5], cv[6], cv[7]);
    }
}

// ---------------- CSR aggregation (layer 2: z + max|z|) ----------------
__global__ __launch_bounds__(256) void k_agg(int layer,
                                             const float* __restrict__ b1_,
                                             const float* __restrict__ b2_,
                                             const float* __restrict__ b3_,
                                             const float* __restrict__ noise) {
    int w = threadIdx.x >> 5, l = threadIdx.x & 31;
    int n = blockIdx.x * 8 + w;
    const float4* in = (layer == 1) ? (const float4*)g_hw1 : (const float4*)g_hw23;
    const float* bLo = (layer == 1) ? b1_ : b2_;
    const float* bHi = (layer == 1) ? b1_ + 64 : b3_;
    const float* bp = (l < 16) ? bLo + l * 4 : bHi + (l - 16) * 4;
    float4 bv = *reinterpret_cast<const float4*>(bp);
    float d = g_dis[n], d2 = d * d;
    float4 h = in[(size_t)n * 32 + l];
    float4 acc = make_float4(bv.x + d2 * h.x, bv.y + d2 * h.y,
                             bv.z + d2 * h.z, bv.w + d2 * h.w);
    int s = g_off[n], cnt = g_cnt[n];
    for (int base = 0; base < cnt; base += 32) {
        int j = base + l;
        int   rr = 0; float ww = 0.f;
        if (j < cnt) { rr = g_crow[s + j]; ww = g_cw[s + j]; }
        int m = cnt - base; if (m > 32) m = 32;
        for (int t = 0; t < m; t++) {
            float wv = __shfl_sync(FULLM, ww, t);
            int   rv = __shfl_sync(FULLM, rr, t);
            float4 vv = in[(size_t)rv * 32 + l];
            acc.x += wv * vv.x; acc.y += wv * vv.y;
            acc.z += wv * vv.z; acc.w += wv * vv.w;
        }
    }
    if (layer == 1) {
        ((float4*)g_h1)[(size_t)n * 32 + l] = acc;
    } else {
        float4 ls;
        ls.x = __shfl_sync(FULLM, acc.x, l | 16);
        ls.y = __shfl_sync(FULLM, acc.y, l | 16);
        ls.z = __shfl_sync(FULLM, acc.z, l | 16);
        ls.w = __shfl_sync(FULLM, acc.w, l | 16);
        if (l < 16) {
            float4 nv = reinterpret_cast<const float4*>(noise)[(size_t)n * 16 + l];
            float z0 = acc.x + nv.x * expf(ls.x);
            float z1 = acc.y + nv.y * expf(ls.y);
            float z2 = acc.z + nv.z * expf(ls.z);
            float z3 = acc.w + nv.w * expf(ls.w);
            reinterpret_cast<float4*>(g_z)[(size_t)n * 16 + l] = make_float4(z0, z1, z2, z3);
            float m = fmaxf(fmaxf(fabsf(z0), fabsf(z1)), fmaxf(fabsf(z2), fabsf(z3)));
#pragma unroll
            for (int o = 8; o; o >>= 1)
                m = fmaxf(m, __shfl_xor_sync(0x0000FFFFu, m, o));
            if (l == 0) atomicMax(&g_smax, __float_as_int(m));
        }
    }
}

// ---------------- quantize z -> int16 split into hi8/lo8 planes ----------------
__global__ void k_quant() {
    int t = blockIdx.x * 256 + threadIdx.x;
    if (t >= NQ * 16) return;
    int row = t >> 4, f = t & 15;
    char4 h4 = make_char4(0, 0, 0, 0), l4 = make_char4(0, 0, 0, 0);
    if (row < N_NODES) {
        float S = fmaxf(__int_as_float(g_smax), 1e-20f);
        float sc = 32000.0f / S;
        float4 z = reinterpret_cast<const float4*>(g_z)[(size_t)row * 16 + f];
        int q, h;
        q = __float2int_rn(z.x * sc); h = (q + 128) >> 8; h4.x = (char)h; l4.x = (char)(q - (h << 8));
        q = __float2int_rn(z.y * sc); h = (q + 128) >> 8; h4.y = (char)h; l4.y = (char)(q - (h << 8));
        q = __float2int_rn(z.z * sc); h = (q + 128) >> 8; h4.z = (char)h; l4.z = (char)(q - (h << 8));
        q = __float2int_rn(z.w * sc); h = (q + 128) >> 8; h4.w = (char)h; l4.w = (char)(q - (h << 8));
    }
    *reinterpret_cast<char4*>(g_q + (size_t)row * 128 + f * 4)      = h4;
    *reinterpret_cast<char4*>(g_q + (size_t)row * 128 + 64 + f * 4) = l4;
}

// ---------------- int8 mma.sync decoder ----------------
__device__ __forceinline__ uint32_t s2u(const void* p) {
    uint32_t a;
    asm("{ .reg .u64 t; cvta.to.shared.u64 t, %1; cvt.u32.u64 %0, t; }" : "=r"(a) : "l"(p));
    return a;
}
__device__ __forceinline__ void ldsm4(uint32_t* r, uint32_t addr) {
    asm volatile("ldmatrix.sync.aligned.m8n8.x4.shared.b16 {%0,%1,%2,%3}, [%4];"
        : "=r"(r[0]), "=r"(r[1]), "=r"(r[2]), "=r"(r[3]) : "r"(addr));
}
__device__ __forceinline__ void ldsm2(uint32_t* r, uint32_t addr) {
    asm volatile("ldmatrix.sync.aligned.m8n8.x2.shared.b16 {%0,%1}, [%2];"
        : "=r"(r[0]), "=r"(r[1]) : "r"(addr));
}
__device__ __forceinline__ void imma(int* d, const uint32_t* a, const uint32_t* b) {
    asm volatile("mma.sync.aligned.m16n8k32.row.col.s32.s8.s8.s32 "
        "{%0,%1,%2,%3}, {%4,%5,%6,%7}, {%8,%9}, {%0,%1,%2,%3};"
        : "+r"(d[0]), "+r"(d[1]), "+r"(d[2]), "+r"(d[3])
        : "r"(a[0]), "r"(a[1]), "r"(a[2]), "r"(a[3]), "r"(b[0]), "r"(b[1]));
}
__device__ __forceinline__ float sigf(float x) {
    float t;
    asm("tanh.approx.f32 %0, %1;" : "=f"(t) : "f"(x * 0.5f));
    return fmaf(t, 0.5f, 0.5f);
}

#define QSTR 144                 // smem row stride (128B data + 16 pad) — conflict-free ldmatrix
#define PT2  68                  // mirror staging pitch (floats)

__global__ __launch_bounds__(256, 2) void k_decoder(float* __restrict__ out) {
    int bj = blockIdx.x, bi = blockIdx.y;
    if (bj < bi) return;
    __shared__ __align__(16) char sm[2 * 64 * QSTR];   // 18432 B: A tile | B tile
    uint32_t sb = s2u(sm);
    int tid = threadIdx.x, lane = tid & 31, wid = tid >> 5;
    int wm = wid >> 2, wn = wid & 3;                   // 2(M) x 4(N); warp tile 32x16
    int rb = bi * 64, cb = bj * 64;

    float Sf = __int_as_float(g_smax) * (1.0f / 32000.0f);
    float inv = Sf * Sf;

    // load A rows (layout [hi|lo]) and B rows (halves swapped -> [lo|hi])
    const uint4* q4 = reinterpret_cast<const uint4*>(g_q);
#pragma unroll
    for (int i = 0; i < 4; i++) {
        int idx = tid + i * 256;                       // 1024 uint4
        int isB = idx >> 9, rem = idx & 511;
        int r = rem >> 3, c = rem & 7;
        int grow = (isB ? cb : rb) + r;                // always < NQ
        uint4 v = q4[(size_t)grow * 8 + c];
        int dc = isB ? ((c + 4) & 7) : c;
        *reinterpret_cast<uint4*>(sm + isB * (64 * QSTR) + r * QSTR + dc * 16) = v;
    }
    __syncthreads();

    uint32_t Ab = sb, Bb = sb + 64 * QSTR;
    int lrow = lane & 15, ksel = lane >> 4;
    int brow = lane & 7,  bsel = (lane >> 3) & 1;

    // preload all B fragments: 4 chunks x 2 nt  (chunks 0,1 = lo; 2,3 = hi)
    uint32_t bb[4][2][2];
#pragma unroll
    for (int ch = 0; ch < 4; ch++)
#pragma unroll
        for (int nt = 0; nt < 2; nt++)
            ldsm2(bb[ch][nt], Bb + (wn * 16 + nt * 8 + brow) * QSTR + ch * 32 + bsel * 16);

    int accH[2][2][4] = {}, accC[2][2][4] = {}, accL[2][2][4] = {};
#pragma unroll
    for (int ch = 0; ch < 4; ch++) {                   // A chunks 0,1 = hi; 2,3 = lo
        uint32_t af[2][4];
#pragma unroll
        for (int mt = 0; mt < 2; mt++)
            ldsm4(af[mt], Ab + (wm * 32 + mt * 16 + lrow) * QSTR + ch * 32 + ksel * 16);
#pragma unroll
        for (int mt = 0; mt < 2; mt++)
#pragma unroll
            for (int nt = 0; nt < 2; nt++) {
                if (ch < 2) {
                    imma(accH[mt][nt], af[mt], bb[ch + 2][nt]);  // hi·hi
                    imma(accC[mt][nt], af[mt], bb[ch][nt]);      // hi·lo
                } else {
                    imma(accC[mt][nt], af[mt], bb[ch][nt]);      // lo·hi
                    imma(accL[mt][nt], af[mt], bb[ch - 2][nt]);  // lo·lo
                }
            }
    }

    // combine + sigmoid
    float v[2][2][4];
#pragma unroll
    for (int mt = 0; mt < 2; mt++)
#pragma unroll
        for (int nt = 0; nt < 2; nt++)
#pragma unroll
            for (int q = 0; q < 4; q++) {
                float lg = fmaf(65536.f, (float)accH[mt][nt][q],
                           fmaf(256.f,   (float)accC[mt][nt][q],
                                         (float)accL[mt][nt][q])) * inv;
                v[mt][nt][q] = sigf(lg);
            }

    // direct stores (coalesced float2)
    int tr = lane >> 2, tc = (lane & 3) * 2;
    bool diag = (bi == bj);
#pragma unroll
    for (int mt = 0; mt < 2; mt++) {
        int r0 = rb + wm * 32 + mt * 16 + tr;
        int r1 = r0 + 8;
#pragma unroll
        for (int nt = 0; nt < 2; nt++) {
            int cc = cb + wn * 16 + nt * 8 + tc;
            if (r0 < N_NODES) {
                if (cc + 1 < N_NODES)
                    *reinterpret_cast<float2*>(out + (size_t)r0 * N_NODES + cc) =
                        make_float2(v[mt][nt][0], v[mt][nt][1]);
                else if (cc < N_NODES)
                    out[(size_t)r0 * N_NODES + cc] = v[mt][nt][0];
            }
            if (r1 < N_NODES) {
                if (cc + 1 < N_NODES)
                    *reinterpret_cast<float2*>(out + (size_t)r1 * N_NODES + cc) =
                        make_float2(v[mt][nt][2], v[mt][nt][3]);
                else if (cc < N_NODES)
                    out[(size_t)r1 * N_NODES + cc] = v[mt][nt][2];
            }
        }
    }

    // mirror tile via smem transpose -> coalesced writes
    if (!diag) {
        __syncthreads();                               // ldmatrix consumers done
        float* stT = reinterpret_cast<float*>(sm);     // [64 cols][PT2]
#pragma unroll
        for (int mt = 0; mt < 2; mt++) {
            int r0 = wm * 32 + mt * 16 + tr, r1 = r0 + 8;
#pragma unroll
            for (int nt = 0; nt < 2; nt++) {
                int lc = wn * 16 + nt * 8 + tc;
                stT[lc * PT2 + r0]       = v[mt][nt][0];
                stT[(lc + 1) * PT2 + r0] = v[mt][nt][1];
                stT[lc * PT2 + r1]       = v[mt][nt][2];
                stT[(lc + 1) * PT2 + r1] = v[mt][nt][3];
            }
        }
        __syncthreads();
        bool fullR = (rb + 64 <= N_NODES);
#pragma unroll
        for (int it = 0; it < 4; it++) {
            int j = wid * 8 + it * 2 + (lane >> 4);
            int gr = cb + j;
            if (gr < N_NODES) {
                float4 vv = *reinterpret_cast<const float4*>(stT + j * PT2 + (lane & 15) * 4);
                float* p = out + (size_t)gr * N_NODES + rb + (lane & 15) * 4;
                if (fullR) {
                    *reinterpret_cast<float4*>(p) = vv;
                } else {
                    int c0 = rb + (lane & 15) * 4;
                    if (c0 + 0 < N_NODES) p[0] = vv.x;
                    if (c0 + 1 < N_NODES) p[1] = vv.y;
                    if (c0 + 2 < N_NODES) p[2] = vv.z;
                    if (c0 + 3 < N_NODES) p[3] = vv.w;
                }
            }
        }
    }
}

// ---------------- launch ----------------
extern "C" void kernel_launch(void* const* d_in, const int* in_sizes, int n_in,
                              void* d_out, int out_size) {
    const float* x     = (const float*)d_in[0];
    const int*   ei    = (const int*)  d_in[1];
    const float* ew    = (const float*)d_in[2];
    const float* noise = (const float*)d_in[3];
    const float* W1    = (const float*)d_in[4];
    const float* b1    = (const float*)d_in[5];
    const float* W2    = (const float*)d_in[6];
    const float* b2    = (const float*)d_in[7];
    const float* W3    = (const float*)d_in[8];
    const float* b3    = (const float*)d_in[9];
    float* out = (float*)d_out;

    k_prep     <<<40, 256>>>();                            // 0
    k_deg_gemm1<<<938, 256>>>(ei, ew, x, W1);              // 1
    k_offsets  <<<40, 256>>>();                            // 2
    k_decoder  <<<dim3(1, 1), 256>>>(out);                 // 3  <- 1-CTA PROBE (profiled; overwritten)
    k_scatter  <<<625, 256>>>(ei, ew);                     // 4
    k_agg      <<<1250, 256>>>(1, b1, b2, b3, noise);      // 5
    k_gemm23   <<<313, 256>>>(W2, W3);                     // 6
    k_agg      <<<1250, 256>>>(2, b1, b2, b3, noise);      // 7
    k_quant    <<<628, 256>>>();                           // 8
    dim3 g(157, 157);
    k_decoder  <<<g, 256>>>(out);                          // 9
}

// round 14
// speedup vs baseline: 1.4742x; 1.4742x over previous
#include <cuda_runtime.h>
#include <cuda_fp16.h>
#include <math.h>
#include <stdint.h>

typedef unsigned long long ull;

#define N_NODES 10000
#define NPAD1   10112          // 79 * 128
#define E_EDGES 160000
#define D_IN    256
#define H1      128
#define H2      64
#define NT      79
#define FULLM   0xFFFFFFFFu

// ---------------- scratch (device globals) ----------------
__device__ float g_dis [N_NODES];
__device__ int   g_cnt [N_NODES];
__device__ int   g_off [N_NODES];
__device__ int   g_cur [N_NODES];
__device__ int   g_total;
__device__ int   g_crow[E_EDGES];
__device__ float g_cw  [E_EDGES];
__device__ float g_hw1 [NPAD1 * H1];
__device__ float g_h1  [NPAD1 * H1];
__device__ float g_hw23[NPAD1 * H1];
__device__ __align__(16) __half g_zhi[NPAD1 * H2];   // pad rows stay 0
__device__ __align__(16) __half g_zlo[NPAD1 * H2];

// ---------------- prep ----------------
__global__ void k_prep() {
    int i = blockIdx.x * 256 + threadIdx.x;
    if (i < N_NODES) { g_dis[i] = 1.0f; g_cnt[i] = 0; }
    if (i == 0) g_total = 0;
}

// ---------------- f32x2 inner product over a 32-K chunk ----------------
template<int TM>
__device__ __forceinline__ void mma32(const float* __restrict__ As,
                                      const float* __restrict__ Bs,
                                      int ty, int tx, ull (&acc)[TM][4]) {
#pragma unroll
    for (int k = 0; k < 32; k++) {
        ulonglong2 p0 = *reinterpret_cast<const ulonglong2*>(Bs + k * 132 + tx * 8);
        ulonglong2 p1 = *reinterpret_cast<const ulonglong2*>(Bs + k * 132 + tx * 8 + 4);
        ull b[4] = {p0.x, p0.y, p1.x, p1.y};
#pragma unroll
        for (int i = 0; i < TM; i++) {
            float a = As[(ty * TM + i) * 36 + k];
            ull ad;
            asm("mov.b64 %0, {%1, %1};" : "=l"(ad) : "f"(a));
#pragma unroll
            for (int jp = 0; jp < 4; jp++)
                asm("fma.rn.f32x2 %0, %1, %2, %0;" : "+l"(acc[i][jp]) : "l"(ad), "l"(b[jp]));
        }
    }
}

// ---------------- fused: degree-count edges (blocks 0..624) + GEMM1 ----------------
__global__ __launch_bounds__(256) void k_deg_gemm1(const int* __restrict__ ei,
                                                   const float* __restrict__ ew,
                                                   const float* __restrict__ x,
                                                   const float* __restrict__ W1) {
    __shared__ __align__(16) float As[32 * 36];
    __shared__ __align__(16) float Bs[32 * 132];
    if (blockIdx.x < 625) {
        int e = blockIdx.x * 256 + threadIdx.x;
        if (e < E_EDGES) {
            int c = ei[E_EDGES + e];
            atomicAdd(&g_dis[c], ew[e]);
            atomicAdd(&g_cnt[c], 1);
        }
        return;
    }
    int tid = threadIdx.x, tx = tid & 15, ty = tid >> 4;
    int mb = (blockIdx.x - 625) * 32;
    float4 pa, pb[4];
    {
        int m = tid >> 3, k4 = tid & 7;
        pa = make_float4(0.f, 0.f, 0.f, 0.f);
        if (mb + m < N_NODES)
            pa = *reinterpret_cast<const float4*>(x + (size_t)(mb + m) * D_IN + k4 * 4);
    }
#pragma unroll
    for (int r = 0; r < 4; r++) {
        int idx = tid + r * 256, kk = idx >> 5, n4 = idx & 31;
        pb[r] = *reinterpret_cast<const float4*>(W1 + (size_t)kk * H1 + n4 * 4);
    }
    ull acc[2][4] = {};
    for (int c = 0; c < 8; c++) {
        {
            int m = tid >> 3, k4 = tid & 7;
            *reinterpret_cast<float4*>(As + m * 36 + k4 * 4) = pa;
        }
#pragma unroll
        for (int r = 0; r < 4; r++) {
            int idx = tid + r * 256, kk = idx >> 5, n4 = idx & 31;
            *reinterpret_cast<float4*>(Bs + kk * 132 + n4 * 4) = pb[r];
        }
        __syncthreads();
        if (c < 7) {
            int kc = (c + 1) * 32;
            int m = tid >> 3, k4 = tid & 7;
            pa = make_float4(0.f, 0.f, 0.f, 0.f);
            if (mb + m < N_NODES)
                pa = *reinterpret_cast<const float4*>(x + (size_t)(mb + m) * D_IN + kc + k4 * 4);
#pragma unroll
            for (int r = 0; r < 4; r++) {
                int idx = tid + r * 256, kk = idx >> 5, n4 = idx & 31;
                pb[r] = *reinterpret_cast<const float4*>(W1 + (size_t)(kc + kk) * H1 + n4 * 4);
            }
        }
        mma32<2>(As, Bs, ty, tx, acc);
        __syncthreads();
    }
#pragma unroll
    for (int i = 0; i < 2; i++) {
        int row = mb + ty * 2 + i;
        float cv[8];
#pragma unroll
        for (int jp = 0; jp < 4; jp++)
            asm("mov.b64 {%0, %1}, %2;" : "=f"(cv[jp*2]), "=f"(cv[jp*2+1]) : "l"(acc[i][jp]));
        float4* p = reinterpret_cast<float4*>(g_hw1 + (size_t)row * H1 + tx * 8);
        p[0] = make_float4(cv[0], cv[1], cv[2], cv[3]);
        p[1] = make_float4(cv[4], cv[5], cv[6], cv[7]);
    }
}

// ---------------- offsets ----------------
__global__ void k_offsets() {
    __shared__ int s[256];
    __shared__ int sbase;
    int t = threadIdx.x;
    int i = blockIdx.x * 256 + t;
    int v = (i < N_NODES) ? g_cnt[i] : 0;
    s[t] = v; __syncthreads();
    for (int d = 1; d < 256; d <<= 1) {
        int x = (t >= d) ? s[t - d] : 0;
        __syncthreads();
        s[t] += x;
        __syncthreads();
    }
    if (t == 255) sbase = atomicAdd(&g_total, s[255]);
    __syncthreads();
    if (i < N_NODES) {
        int off = sbase + s[t] - v;
        g_off[i] = off; g_cur[i] = off;
        g_dis[i] = rsqrtf(g_dis[i]);
    }
}
__global__ void k_scatter(const int* __restrict__ ei, const float* __restrict__ ew) {
    int e = blockIdx.x * 256 + threadIdx.x;
    if (e < E_EDGES) {
        int r = ei[e], c = ei[E_EDGES + e];
        int p = atomicAdd(&g_cur[c], 1);
        g_crow[p] = r;
        g_cw[p]   = g_dis[r] * ew[e] * g_dis[c];
    }
}

// ---------------- GEMM23 ----------------
__global__ __launch_bounds__(256) void k_gemm23(const float* __restrict__ W2,
                                                const float* __restrict__ W3) {
    __shared__ __align__(16) float As[32 * 36];
    __shared__ __align__(16) float Bs[32 * 132];
    int tid = threadIdx.x, tx = tid & 15, ty = tid >> 4;
    int mb = blockIdx.x * 32;
    float4 pa, pb[4];
    {
        int m = tid >> 3, k4 = tid & 7;
        float4 v = *reinterpret_cast<const float4*>(g_h1 + (size_t)(mb + m) * H1 + k4 * 4);
        pa = make_float4(fmaxf(v.x, 0.f), fmaxf(v.y, 0.f), fmaxf(v.z, 0.f), fmaxf(v.w, 0.f));
    }
#pragma unroll
    for (int r = 0; r < 4; r++) {
        int idx = tid + r * 256, kk = idx >> 5, n4 = idx & 31;
        pb[r] = (n4 < 16)
            ? *reinterpret_cast<const float4*>(W2 + (size_t)kk * H2 + n4 * 4)
            : *reinterpret_cast<const float4*>(W3 + (size_t)kk * H2 + (n4 - 16) * 4);
    }
    ull acc[2][4] = {};
    for (int c = 0; c < 4; c++) {
        {
            int m = tid >> 3, k4 = tid & 7;
            *reinterpret_cast<float4*>(As + m * 36 + k4 * 4) = pa;
        }
#pragma unroll
        for (int r = 0; r < 4; r++) {
            int idx = tid + r * 256, kk = idx >> 5, n4 = idx & 31;
            *reinterpret_cast<float4*>(Bs + kk * 132 + n4 * 4) = pb[r];
        }
        __syncthreads();
        if (c < 3) {
            int kc = (c + 1) * 32;
            int m = tid >> 3, k4 = tid & 7;
            float4 v = *reinterpret_cast<const float4*>(g_h1 + (size_t)(mb + m) * H1 + kc + k4 * 4);
            pa = make_float4(fmaxf(v.x, 0.f), fmaxf(v.y, 0.f), fmaxf(v.z, 0.f), fmaxf(v.w, 0.f));
#pragma unroll
            for (int r = 0; r < 4; r++) {
                int idx = tid + r * 256, kk = idx >> 5, n4 = idx & 31;
                pb[r] = (n4 < 16)
                    ? *reinterpret_cast<const float4*>(W2 + (size_t)(kc + kk) * H2 + n4 * 4)
                    : *reinterpret_cast<const float4*>(W3 + (size_t)(kc + kk) * H2 + (n4 - 16) * 4);
            }
        }
        mma32<2>(As, Bs, ty, tx, acc);
        __syncthreads();
    }
#pragma unroll
    for (int i = 0; i < 2; i++) {
        int row = mb + ty * 2 + i;
        float cv[8];
#pragma unroll
        for (int jp = 0; jp < 4; jp++)
            asm("mov.b64 {%0, %1}, %2;" : "=f"(cv[jp*2]), "=f"(cv[jp*2+1]) : "l"(acc[i][jp]));
        float4* p = reinterpret_cast<float4*>(g_hw23 + (size_t)row * H1 + tx * 8);
        p[0] = make_float4(cv[0], cv[1], cv[2], cv[3]);
        p[1] = make_float4(cv[4], cv[5], cv[6], cv[7]);
    }
}

// ---------------- CSR aggregation (layer 2 fuses z + fp16 hi/lo split) ----------------
__global__ __launch_bounds__(256) void k_agg(int layer,
                                             const float* __restrict__ b1_,
                                             const float* __restrict__ b2_,
                                             const float* __restrict__ b3_,
                                             const float* __restrict__ noise) {
    int w = threadIdx.x >> 5, l = threadIdx.x & 31;
    int n = blockIdx.x * 8 + w;
    const float4* in = (layer == 1) ? (const float4*)g_hw1 : (const float4*)g_hw23;
    const float* bLo = (layer == 1) ? b1_ : b2_;
    const float* bHi = (layer == 1) ? b1_ + 64 : b3_;
    const float* bp = (l < 16) ? bLo + l * 4 : bHi + (l - 16) * 4;
    float4 bv = *reinterpret_cast<const float4*>(bp);
    float d = g_dis[n], d2 = d * d;
    float4 h = in[(size_t)n * 32 + l];
    float4 acc = make_float4(bv.x + d2 * h.x, bv.y + d2 * h.y,
                             bv.z + d2 * h.z, bv.w + d2 * h.w);
    int s = g_off[n], cnt = g_cnt[n];
    for (int base = 0; base < cnt; base += 32) {
        int j = base + l;
        int   rr = 0; float ww = 0.f;
        if (j < cnt) { rr = g_crow[s + j]; ww = g_cw[s + j]; }
        int m = cnt - base; if (m > 32) m = 32;
        for (int t = 0; t < m; t++) {
            float wv = __shfl_sync(FULLM, ww, t);
            int   rv = __shfl_sync(FULLM, rr, t);
            float4 vv = in[(size_t)rv * 32 + l];
            acc.x += wv * vv.x; acc.y += wv * vv.y;
            acc.z += wv * vv.z; acc.w += wv * vv.w;
        }
    }
    if (layer == 1) {
        ((float4*)g_h1)[(size_t)n * 32 + l] = acc;
    } else {
        float4 ls;
        ls.x = __shfl_sync(FULLM, acc.x, l | 16);
        ls.y = __shfl_sync(FULLM, acc.y, l | 16);
        ls.z = __shfl_sync(FULLM, acc.z, l | 16);
        ls.w = __shfl_sync(FULLM, acc.w, l | 16);
        if (l < 16) {
            float4 nv = reinterpret_cast<const float4*>(noise)[(size_t)n * 16 + l];
            float z0 = acc.x + nv.x * expf(ls.x);
            float z1 = acc.y + nv.y * expf(ls.y);
            float z2 = acc.z + nv.z * expf(ls.z);
            float z3 = acc.w + nv.w * expf(ls.w);
            // clamp for fp16 range (only affects fully saturated sigmoid outputs)
            z0 = fminf(fmaxf(z0, -60000.f), 60000.f);
            z1 = fminf(fmaxf(z1, -60000.f), 60000.f);
            z2 = fminf(fmaxf(z2, -60000.f), 60000.f);
            z3 = fminf(fmaxf(z3, -60000.f), 60000.f);
            __half h0 = __float2half(z0), h1 = __float2half(z1);
            __half h2 = __float2half(z2), h3 = __float2half(z3);
            __half l0 = __float2half(z0 - __half2float(h0));
            __half l1 = __float2half(z1 - __half2float(h1));
            __half l2 = __float2half(z2 - __half2float(h2));
            __half l3 = __float2half(z3 - __half2float(h3));
            uint2 ph, pl;
            ph.x = ((uint32_t)__half_as_ushort(h1) << 16) | __half_as_ushort(h0);
            ph.y = ((uint32_t)__half_as_ushort(h3) << 16) | __half_as_ushort(h2);
            pl.x = ((uint32_t)__half_as_ushort(l1) << 16) | __half_as_ushort(l0);
            pl.y = ((uint32_t)__half_as_ushort(l3) << 16) | __half_as_ushort(l2);
            reinterpret_cast<uint2*>(g_zhi)[(size_t)n * 16 + l] = ph;
            reinterpret_cast<uint2*>(g_zlo)[(size_t)n * 16 + l] = pl;
        }
    }
}

// ---------------- fp16 single-pass mma.sync decoder ----------------
__device__ __forceinline__ uint32_t s2u(const void* p) {
    uint32_t a;
    asm("{ .reg .u64 t; cvta.to.shared.u64 t, %1; cvt.u32.u64 %0, t; }" : "=r"(a) : "l"(p));
    return a;
}
__device__ __forceinline__ void ldsm4(uint32_t* r, uint32_t addr) {
    asm volatile("ldmatrix.sync.aligned.m8n8.x4.shared.b16 {%0,%1,%2,%3}, [%4];"
        : "=r"(r[0]), "=r"(r[1]), "=r"(r[2]), "=r"(r[3]) : "r"(addr));
}
__device__ __forceinline__ void ldsm2(uint32_t* r, uint32_t addr) {
    asm volatile("ldmatrix.sync.aligned.m8n8.x2.shared.b16 {%0,%1}, [%2];"
        : "=r"(r[0]), "=r"(r[1]) : "r"(addr));
}
__device__ __forceinline__ void hmma(float* d, const uint32_t* a, const uint32_t* b) {
    asm volatile("mma.sync.aligned.m16n8k16.row.col.f32.f16.f16.f32 "
        "{%0,%1,%2,%3}, {%4,%5,%6,%7}, {%8,%9}, {%0,%1,%2,%3};"
        : "+f"(d[0]), "+f"(d[1]), "+f"(d[2]), "+f"(d[3])
        : "r"(a[0]), "r"(a[1]), "r"(a[2]), "r"(a[3]), "r"(b[0]), "r"(b[1]));
}
__device__ __forceinline__ float sigf(float x) {
    float t;
    asm("tanh.approx.f32 %0, %1;" : "=f"(t) : "f"(x * 0.5f));
    return fmaf(t, 0.5f, 0.5f);
}

#define ABYTES 272                 // A row: [hi(128B) | lo(128B)] + 16 pad
#define BBYTES 144                 // B row: hi(128B) + 16 pad
#define A_SZ   (128 * ABYTES)      // 34816
#define PT     132
#define DEC_SMEM 67584             // >= max(A_SZ + 128*BBYTES, 128*PT*4)

__global__ __launch_bounds__(256, 2) void k_decoder(float* __restrict__ out) {
    int bj = blockIdx.x, bi = blockIdx.y;
    if (bj < bi) return;
    extern __shared__ char sm[];
    uint32_t sb = s2u(sm);
    char* smB = sm + A_SZ;
    int tid = threadIdx.x, lane = tid & 31, wid = tid >> 5;
    int wm = wid >> 2, wn = wid & 3;                   // 2(M) x 4(N); warp 64x32
    int rb = bi * 128, cb = bj * 128;

    const uint4* zh = reinterpret_cast<const uint4*>(g_zhi);
    const uint4* zl = reinterpret_cast<const uint4*>(g_zlo);
#pragma unroll
    for (int i = 0; i < 12; i++) {                     // 3072 uint4
        int idx = tid + i * 256;
        if (idx < 2048) {                              // A: [hi|lo] rows
            int r = idx >> 4, c = idx & 15;
            uint4 v = (c < 8) ? zh[(size_t)(rb + r) * 8 + c]
                              : zl[(size_t)(rb + r) * 8 + (c - 8)];
            *reinterpret_cast<uint4*>(sm + r * ABYTES + c * 16) = v;
        } else {                                       // B: hi rows
            int rem = idx - 2048, r = rem >> 3, c = rem & 7;
            uint4 v = zh[(size_t)(cb + r) * 8 + c];
            *reinterpret_cast<uint4*>(smB + r * BBYTES + c * 16) = v;
        }
    }
    __syncthreads();

    uint32_t Ab = sb, Bb = sb + A_SZ;
    int lrow = lane & 15, ksel = lane >> 4;
    int brow = lane & 7,  bsel = (lane >> 3) & 1;

    float acc[4][4][4] = {};
#pragma unroll
    for (int ch = 0; ch < 8; ch++) {                   // K=128 concat: ch<4 hi·hi, ch>=4 lo·hi
        uint32_t bf[4][2], af[4][4];
#pragma unroll
        for (int nt = 0; nt < 4; nt++)
            ldsm2(bf[nt], Bb + (wn * 32 + nt * 8 + brow) * BBYTES + (ch & 3) * 32 + bsel * 16);
#pragma unroll
        for (int mt = 0; mt < 4; mt++)
            ldsm4(af[mt], Ab + (wm * 64 + mt * 16 + lrow) * ABYTES + ch * 32 + ksel * 16);
#pragma unroll
        for (int mt = 0; mt < 4; mt++)
#pragma unroll
            for (int nt = 0; nt < 4; nt++) hmma(acc[mt][nt], af[mt], bf[nt]);
    }

#pragma unroll
    for (int mt = 0; mt < 4; mt++)
#pragma unroll
        for (int nt = 0; nt < 4; nt++)
#pragma unroll
            for (int q = 0; q < 4; q++) acc[mt][nt][q] = sigf(acc[mt][nt][q]);

    int tr = lane >> 2, tc = (lane & 3) * 2;
    bool diag = (bi == bj);
#pragma unroll
    for (int mt = 0; mt < 4; mt++) {
        int r0 = rb + wm * 64 + mt * 16 + tr;
        int r1 = r0 + 8;
#pragma unroll
        for (int nt = 0; nt < 4; nt++) {
            int cc = cb + wn * 32 + nt * 8 + tc;
            if (r0 < N_NODES) {
                if (cc + 1 < N_NODES)
                    *reinterpret_cast<float2*>(out + (size_t)r0 * N_NODES + cc) =
                        make_float2(acc[mt][nt][0], acc[mt][nt][1]);
                else if (cc < N_NODES)
                    out[(size_t)r0 * N_NODES + cc] = acc[mt][nt][0];
            }
            if (r1 < N_NODES) {
                if (cc + 1 < N_NODES)
                    *reinterpret_cast<float2*>(out + (size_t)r1 * N_NODES + cc) =
                        make_float2(acc[mt][nt][2], acc[mt][nt][3]);
                else if (cc < N_NODES)
                    out[(size_t)r1 * N_NODES + cc] = acc[mt][nt][2];
            }
        }
    }

    // mirror tile via smem transpose -> coalesced float4 row writes
    if (!diag) {
        __syncthreads();
        float* stT = reinterpret_cast<float*>(sm);     // [128 cols][PT]
        int lr0 = wm * 64 + tr;
#pragma unroll
        for (int mt = 0; mt < 4; mt++) {
            int r0 = lr0 + mt * 16, r1 = r0 + 8;
#pragma unroll
            for (int nt = 0; nt < 4; nt++) {
                int lc = wn * 32 + nt * 8 + tc;
                stT[lc * PT + r0]       = acc[mt][nt][0];
                stT[(lc + 1) * PT + r0] = acc[mt][nt][1];
                stT[lc * PT + r1]       = acc[mt][nt][2];
                stT[(lc + 1) * PT + r1] = acc[mt][nt][3];
            }
        }
        __syncthreads();
        bool fullR = (rb + 128 <= N_NODES);
#pragma unroll
        for (int it = 0; it < 16; it++) {
            int j = wid + it * 8;
            int gr = cb + j;
            if (gr < N_NODES) {
                float4 v = *reinterpret_cast<const float4*>(stT + j * PT + lane * 4);
                float* p = out + (size_t)gr * N_NODES + rb + lane * 4;
                if (fullR) {
                    *reinterpret_cast<float4*>(p) = v;
                } else {
                    int c0 = rb + lane * 4;
                    if (c0 + 0 < N_NODES) p[0] = v.x;
                    if (c0 + 1 < N_NODES) p[1] = v.y;
                    if (c0 + 2 < N_NODES) p[2] = v.z;
                    if (c0 + 3 < N_NODES) p[3] = v.w;
                }
            }
        }
    }
}

// ---------------- launch ----------------
extern "C" void kernel_launch(void* const* d_in, const int* in_sizes, int n_in,
                              void* d_out, int out_size) {
    const float* x     = (const float*)d_in[0];
    const int*   ei    = (const int*)  d_in[1];
    const float* ew    = (const float*)d_in[2];
    const float* noise = (const float*)d_in[3];
    const float* W1    = (const float*)d_in[4];
    const float* b1    = (const float*)d_in[5];
    const float* W2    = (const float*)d_in[6];
    const float* b2    = (const float*)d_in[7];
    const float* W3    = (const float*)d_in[8];
    const float* b3    = (const float*)d_in[9];
    float* out = (float*)d_out;

    static int smem_set = 0;
    if (!smem_set) {
        cudaFuncSetAttribute(k_decoder, cudaFuncAttributeMaxDynamicSharedMemorySize, DEC_SMEM);
        smem_set = 1;
    }

    k_prep     <<<40, 256>>>();                            // 0
    k_deg_gemm1<<<938, 256>>>(ei, ew, x, W1);              // 1
    k_offsets  <<<40, 256>>>();                            // 2
    k_scatter  <<<625, 256>>>(ei, ew);                     // 3  <- profiled
    k_agg      <<<1250, 256>>>(1, b1, b2, b3, noise);      // 4
    k_gemm23   <<<313, 256>>>(W2, W3);                     // 5
    k_agg      <<<1250, 256>>>(2, b1, b2, b3, noise);      // 6
    dim3 g(NT, NT);
    k_decoder  <<<g, 256, DEC_SMEM>>>(out);                // 7
}

// round 16
// speedup vs baseline: 1.5526x; 1.0532x over previous
#include <cuda_runtime.h>
#include <cuda_fp16.h>
#include <math.h>
#include <stdint.h>

typedef unsigned long long ull;

#define N_NODES 10000
#define NPAD1   10112          // 79 * 128
#define E_EDGES 160000
#define D_IN    256
#define H1      128
#define H2      64
#define NT      79
#define FULLM   0xFFFFFFFFu

// ---------------- scratch (device globals) ----------------
__device__ float g_dis [N_NODES];
__device__ int   g_cnt [N_NODES];
__device__ int   g_off [N_NODES];
__device__ int   g_cur [N_NODES];
__device__ int   g_total;
__device__ int   g_crow[E_EDGES];
__device__ float g_cw  [E_EDGES];
__device__ float g_hw1 [NPAD1 * H1];
__device__ float g_h1  [NPAD1 * H1];
__device__ float g_hw23[NPAD1 * H1];
__device__ __align__(16) __half g_zhi[NPAD1 * H2];   // pad rows stay 0
// ---------------- prep ----------------
__global__ void k_prep() {
    int i = blockIdx.x * 256 + threadIdx.x;
    if (i < N_NODES) { g_dis[i] = 1.0f; g_cnt[i] = 0; }
    if (i == 0) g_total = 0;
}

// ---------------- f32x2 inner product over a 32-K chunk ----------------
template<int TM>
__device__ __forceinline__ void mma32(const float* __restrict__ As,
                                      const float* __restrict__ Bs,
                                      int ty, int tx, ull (&acc)[TM][4]) {
#pragma unroll
    for (int k = 0; k < 32; k++) {
        ulonglong2 p0 = *reinterpret_cast<const ulonglong2*>(Bs + k * 132 + tx * 8);
        ulonglong2 p1 = *reinterpret_cast<const ulonglong2*>(Bs + k * 132 + tx * 8 + 4);
        ull b[4] = {p0.x, p0.y, p1.x, p1.y};
#pragma unroll
        for (int i = 0; i < TM; i++) {
            float a = As[(ty * TM + i) * 36 + k];
            ull ad;
            asm("mov.b64 %0, {%1, %1};" : "=l"(ad) : "f"(a));
#pragma unroll
            for (int jp = 0; jp < 4; jp++)
                asm("fma.rn.f32x2 %0, %1, %2, %0;" : "+l"(acc[i][jp]) : "l"(ad), "l"(b[jp]));
        }
    }
}

// ---------------- fused: degree-count edges (blocks 0..624) + GEMM1 ----------------
__global__ __launch_bounds__(256) void k_deg_gemm1(const int* __restrict__ ei,
                                                   const float* __restrict__ ew,
                                                   const float* __restrict__ x,
                                                   const float* __restrict__ W1) {
    __shared__ __align__(16) float As[32 * 36];
    __shared__ __align__(16) float Bs[32 * 132];
    if (blockIdx.x < 625) {
        int e = blockIdx.x * 256 + threadIdx.x;
        if (e < E_EDGES) {
            int c = ei[E_EDGES + e];
            atomicAdd(&g_dis[c], ew[e]);
            atomicAdd(&g_cnt[c], 1);
        }
        return;
    }
    int tid = threadIdx.x, tx = tid & 15, ty = tid >> 4;
    int mb = (blockIdx.x - 625) * 32;
    float4 pa, pb[4];
    {
        int m = tid >> 3, k4 = tid & 7;
        pa = make_float4(0.f, 0.f, 0.f, 0.f);
        if (mb + m < N_NODES)
            pa = *reinterpret_cast<const float4*>(x + (size_t)(mb + m) * D_IN + k4 * 4);
    }
#pragma unroll
    for (int r = 0; r < 4; r++) {
        int idx = tid + r * 256, kk = idx >> 5, n4 = idx & 31;
        pb[r] = *reinterpret_cast<const float4*>(W1 + (size_t)kk * H1 + n4 * 4);
    }
    ull acc[2][4] = {};
    for (int c = 0; c < 8; c++) {
        {
            int m = tid >> 3, k4 = tid & 7;
            *reinterpret_cast<float4*>(As + m * 36 + k4 * 4) = pa;
        }
#pragma unroll
        for (int r = 0; r < 4; r++) {
            int idx = tid + r * 256, kk = idx >> 5, n4 = idx & 31;
            *reinterpret_cast<float4*>(Bs + kk * 132 + n4 * 4) = pb[r];
        }
        __syncthreads();
        if (c < 7) {
            int kc = (c + 1) * 32;
            int m = tid >> 3, k4 = tid & 7;
            pa = make_float4(0.f, 0.f, 0.f, 0.f);
            if (mb + m < N_NODES)
                pa = *reinterpret_cast<const float4*>(x + (size_t)(mb + m) * D_IN + kc + k4 * 4);
#pragma unroll
            for (int r = 0; r < 4; r++) {
                int idx = tid + r * 256, kk = idx >> 5, n4 = idx & 31;
                pb[r] = *reinterpret_cast<const float4*>(W1 + (size_t)(kc + kk) * H1 + n4 * 4);
            }
        }
        mma32<2>(As, Bs, ty, tx, acc);
        __syncthreads();
    }
#pragma unroll
    for (int i = 0; i < 2; i++) {
        int row = mb + ty * 2 + i;
        float cv[8];
#pragma unroll
        for (int jp = 0; jp < 4; jp++)
            asm("mov.b64 {%0, %1}, %2;" : "=f"(cv[jp*2]), "=f"(cv[jp*2+1]) : "l"(acc[i][jp]));
        float4* p = reinterpret_cast<float4*>(g_hw1 + (size_t)row * H1 + tx * 8);
        p[0] = make_float4(cv[0], cv[1], cv[2], cv[3]);
        p[1] = make_float4(cv[4], cv[5], cv[6], cv[7]);
    }
}

// ---------------- offsets ----------------
__global__ void k_offsets() {
    __shared__ int s[256];
    __shared__ int sbase;
    int t = threadIdx.x;
    int i = blockIdx.x * 256 + t;
    int v = (i < N_NODES) ? g_cnt[i] : 0;
    s[t] = v; __syncthreads();
    for (int d = 1; d < 256; d <<= 1) {
        int x = (t >= d) ? s[t - d] : 0;
        __syncthreads();
        s[t] += x;
        __syncthreads();
    }
    if (t == 255) sbase = atomicAdd(&g_total, s[255]);
    __syncthreads();
    if (i < N_NODES) {
        int off = sbase + s[t] - v;
        g_off[i] = off; g_cur[i] = off;
        g_dis[i] = rsqrtf(g_dis[i]);
    }
}
__global__ void k_scatter(const int* __restrict__ ei, const float* __restrict__ ew) {
    int e = blockIdx.x * 256 + threadIdx.x;
    if (e < E_EDGES) {
        int r = ei[e], c = ei[E_EDGES + e];
        int p = atomicAdd(&g_cur[c], 1);
        g_crow[p] = r;
        g_cw[p]   = g_dis[r] * ew[e] * g_dis[c];
    }
}

// ---------------- GEMM23 ----------------
__global__ __launch_bounds__(256) void k_gemm23(const float* __restrict__ W2,
                                                const float* __restrict__ W3) {
    __shared__ __align__(16) float As[32 * 36];
    __shared__ __align__(16) float Bs[32 * 132];
    int tid = threadIdx.x, tx = tid & 15, ty = tid >> 4;
    int mb = blockIdx.x * 32;
    float4 pa, pb[4];
    {
        int m = tid >> 3, k4 = tid & 7;
        float4 v = *reinterpret_cast<const float4*>(g_h1 + (size_t)(mb + m) * H1 + k4 * 4);
        pa = make_float4(fmaxf(v.x, 0.f), fmaxf(v.y, 0.f), fmaxf(v.z, 0.f), fmaxf(v.w, 0.f));
    }
#pragma unroll
    for (int r = 0; r < 4; r++) {
        int idx = tid + r * 256, kk = idx >> 5, n4 = idx & 31;
        pb[r] = (n4 < 16)
            ? *reinterpret_cast<const float4*>(W2 + (size_t)kk * H2 + n4 * 4)
            : *reinterpret_cast<const float4*>(W3 + (size_t)kk * H2 + (n4 - 16) * 4);
    }
    ull acc[2][4] = {};
    for (int c = 0; c < 4; c++) {
        {
            int m = tid >> 3, k4 = tid & 7;
            *reinterpret_cast<float4*>(As + m * 36 + k4 * 4) = pa;
        }
#pragma unroll
        for (int r = 0; r < 4; r++) {
            int idx = tid + r * 256, kk = idx >> 5, n4 = idx & 31;
            *reinterpret_cast<float4*>(Bs + kk * 132 + n4 * 4) = pb[r];
        }
        __syncthreads();
        if (c < 3) {
            int kc = (c + 1) * 32;
            int m = tid >> 3, k4 = tid & 7;
            float4 v = *reinterpret_cast<const float4*>(g_h1 + (size_t)(mb + m) * H1 + kc + k4 * 4);
            pa = make_float4(fmaxf(v.x, 0.f), fmaxf(v.y, 0.f), fmaxf(v.z, 0.f), fmaxf(v.w, 0.f));
#pragma unroll
            for (int r = 0; r < 4; r++) {
                int idx = tid + r * 256, kk = idx >> 5, n4 = idx & 31;
                pb[r] = (n4 < 16)
                    ? *reinterpret_cast<const float4*>(W2 + (size_t)(kc + kk) * H2 + n4 * 4)
                    : *reinterpret_cast<const float4*>(W3 + (size_t)(kc + kk) * H2 + (n4 - 16) * 4);
            }
        }
        mma32<2>(As, Bs, ty, tx, acc);
        __syncthreads();
    }
#pragma unroll
    for (int i = 0; i < 2; i++) {
        int row = mb + ty * 2 + i;
        float cv[8];
#pragma unroll
        for (int jp = 0; jp < 4; jp++)
            asm("mov.b64 {%0, %1}, %2;" : "=f"(cv[jp*2]), "=f"(cv[jp*2+1]) : "l"(acc[i][jp]));
        float4* p = reinterpret_cast<float4*>(g_hw23 + (size_t)row * H1 + tx * 8);
        p[0] = make_float4(cv[0], cv[1], cv[2], cv[3]);
        p[1] = make_float4(cv[4], cv[5], cv[6], cv[7]);
    }
}

// ---------------- CSR aggregation (layer 2 fuses z + fp16 quantize) ----------------
__global__ __launch_bounds__(256) void k_agg(int layer,
                                             const float* __restrict__ b1_,
                                             const float* __restrict__ b2_,
                                             const float* __restrict__ b3_,
                                             const float* __restrict__ noise) {
    int w = threadIdx.x >> 5, l = threadIdx.x & 31;
    int n = blockIdx.x * 8 + w;
    const float4* in = (layer == 1) ? (const float4*)g_hw1 : (const float4*)g_hw23;
    const float* bLo = (layer == 1) ? b1_ : b2_;
    const float* bHi = (layer == 1) ? b1_ + 64 : b3_;
    const float* bp = (l < 16) ? bLo + l * 4 : bHi + (l - 16) * 4;
    float4 bv = *reinterpret_cast<const float4*>(bp);
    float d = g_dis[n], d2 = d * d;
    float4 h = in[(size_t)n * 32 + l];
    float4 acc = make_float4(bv.x + d2 * h.x, bv.y + d2 * h.y,
                             bv.z + d2 * h.z, bv.w + d2 * h.w);
    int s = g_off[n], cnt = g_cnt[n];
    for (int base = 0; base < cnt; base += 32) {
        int j = base + l;
        int   rr = 0; float ww = 0.f;
        if (j < cnt) { rr = g_crow[s + j]; ww = g_cw[s + j]; }
        int m = cnt - base; if (m > 32) m = 32;
        for (int t = 0; t < m; t++) {
            float wv = __shfl_sync(FULLM, ww, t);
            int   rv = __shfl_sync(FULLM, rr, t);
            float4 vv = in[(size_t)rv * 32 + l];
            acc.x += wv * vv.x; acc.y += wv * vv.y;
            acc.z += wv * vv.z; acc.w += wv * vv.w;
        }
    }
    if (layer == 1) {
        ((float4*)g_h1)[(size_t)n * 32 + l] = acc;
    } else {
        float4 ls;
        ls.x = __shfl_sync(FULLM, acc.x, l | 16);
        ls.y = __shfl_sync(FULLM, acc.y, l | 16);
        ls.z = __shfl_sync(FULLM, acc.z, l | 16);
        ls.w = __shfl_sync(FULLM, acc.w, l | 16);
        if (l < 16) {
            float4 nv = reinterpret_cast<const float4*>(noise)[(size_t)n * 16 + l];
            float z0 = acc.x + nv.x * expf(ls.x);
            float z1 = acc.y + nv.y * expf(ls.y);
            float z2 = acc.z + nv.z * expf(ls.z);
            float z3 = acc.w + nv.w * expf(ls.w);
            z0 = fminf(fmaxf(z0, -60000.f), 60000.f);
            z1 = fminf(fmaxf(z1, -60000.f), 60000.f);
            z2 = fminf(fmaxf(z2, -60000.f), 60000.f);
            z3 = fminf(fmaxf(z3, -60000.f), 60000.f);
            __half h0 = __float2half(z0), h1 = __float2half(z1);
            __half h2 = __float2half(z2), h3 = __float2half(z3);
            uint2 ph;
            ph.x = ((uint32_t)__half_as_ushort(h1) << 16) | __half_as_ushort(h0);
            ph.y = ((uint32_t)__half_as_ushort(h3) << 16) | __half_as_ushort(h2);
            reinterpret_cast<uint2*>(g_zhi)[(size_t)n * 16 + l] = ph;
        }
    }
}

// ---------------- fp16 hi-only (K=64) mma.sync decoder ----------------
__device__ __forceinline__ uint32_t s2u(const void* p) {
    uint32_t a;
    asm("{ .reg .u64 t; cvta.to.shared.u64 t, %1; cvt.u32.u64 %0, t; }" : "=r"(a) : "l"(p));
    return a;
}
__device__ __forceinline__ void ldsm4(uint32_t* r, uint32_t addr) {
    asm volatile("ldmatrix.sync.aligned.m8n8.x4.shared.b16 {%0,%1,%2,%3}, [%4];"
        : "=r"(r[0]), "=r"(r[1]), "=r"(r[2]), "=r"(r[3]) : "r"(addr));
}
__device__ __forceinline__ void ldsm2(uint32_t* r, uint32_t addr) {
    asm volatile("ldmatrix.sync.aligned.m8n8.x2.shared.b16 {%0,%1}, [%2];"
        : "=r"(r[0]), "=r"(r[1]) : "r"(addr));
}
__device__ __forceinline__ void hmma(float* d, const uint32_t* a, const uint32_t* b) {
    asm volatile("mma.sync.aligned.m16n8k16.row.col.f32.f16.f16.f32 "
        "{%0,%1,%2,%3}, {%4,%5,%6,%7}, {%8,%9}, {%0,%1,%2,%3};"
        : "+f"(d[0]), "+f"(d[1]), "+f"(d[2]), "+f"(d[3])
        : "r"(a[0]), "r"(a[1]), "r"(a[2]), "r"(a[3]), "r"(b[0]), "r"(b[1]));
}
__device__ __forceinline__ float sigf(float x) {
    float t;
    asm("tanh.approx.f32 %0, %1;" : "=f"(t) : "f"(x * 0.5f));
    return fmaf(t, 0.5f, 0.5f);
}

#define RSTR 144                   // tile row stride: 128B data + 16 pad (conflict-free)
#define T_SZ (128 * RSTR)          // 18432 per tile
#define PT   132
#define DEC_SMEM 67584             // >= max(2*T_SZ, 128*PT*4)

__global__ __launch_bounds__(256, 2) void k_decoder(float* __restrict__ out) {
    int bj = blockIdx.x, bi = blockIdx.y;
    if (bj < bi) return;
    extern __shared__ char sm[];
    uint32_t sb = s2u(sm);
    char* smB = sm + T_SZ;
    int tid = threadIdx.x, lane = tid & 31, wid = tid >> 5;
    int wm = wid >> 2, wn = wid & 3;                   // 2(M) x 4(N); warp 64x32
    int rb = bi * 128, cb = bj * 128;

    const uint4* zh = reinterpret_cast<const uint4*>(g_zhi);
#pragma unroll
    for (int i = 0; i < 8; i++) {                      // 2048 uint4
        int idx = tid + i * 256;
        int isB = idx >> 10, rem = idx & 1023;
        int r = rem >> 3, c = rem & 7;
        uint4 v = zh[(size_t)((isB ? cb : rb) + r) * 8 + c];
        *reinterpret_cast<uint4*>((isB ? smB : sm) + r * RSTR + c * 16) = v;
    }
    __syncthreads();

    uint32_t Ab = sb, Bb = sb + T_SZ;
    int lrow = lane & 15, ksel = lane >> 4;
    int brow = lane & 7,  bsel = (lane >> 3) & 1;

    float acc[4][4][4] = {};
#pragma unroll
    for (int ch = 0; ch < 4; ch++) {                   // K=64: hi·hi only
        uint32_t bf[4][2], af[4][4];
#pragma unroll
        for (int nt = 0; nt < 4; nt++)
            ldsm2(bf[nt], Bb + (wn * 32 + nt * 8 + brow) * RSTR + ch * 32 + bsel * 16);
#pragma unroll
        for (int mt = 0; mt < 4; mt++)
            ldsm4(af[mt], Ab + (wm * 64 + mt * 16 + lrow) * RSTR + ch * 32 + ksel * 16);
#pragma unroll
        for (int mt = 0; mt < 4; mt++)
#pragma unroll
            for (int nt = 0; nt < 4; nt++) hmma(acc[mt][nt], af[mt], bf[nt]);
    }

#pragma unroll
    for (int mt = 0; mt < 4; mt++)
#pragma unroll
        for (int nt = 0; nt < 4; nt++)
#pragma unroll
            for (int q = 0; q < 4; q++) acc[mt][nt][q] = sigf(acc[mt][nt][q]);

    int tr = lane >> 2, tc = (lane & 3) * 2;
    bool diag = (bi == bj);
#pragma unroll
    for (int mt = 0; mt < 4; mt++) {
        int r0 = rb + wm * 64 + mt * 16 + tr;
        int r1 = r0 + 8;
#pragma unroll
        for (int nt = 0; nt < 4; nt++) {
            int cc = cb + wn * 32 + nt * 8 + tc;
            if (r0 < N_NODES) {
                if (cc + 1 < N_NODES)
                    *reinterpret_cast<float2*>(out + (size_t)r0 * N_NODES + cc) =
                        make_float2(acc[mt][nt][0], acc[mt][nt][1]);
                else if (cc < N_NODES)
                    out[(size_t)r0 * N_NODES + cc] = acc[mt][nt][0];
            }
            if (r1 < N_NODES) {
                if (cc + 1 < N_NODES)
                    *reinterpret_cast<float2*>(out + (size_t)r1 * N_NODES + cc) =
                        make_float2(acc[mt][nt][2], acc[mt][nt][3]);
                else if (cc < N_NODES)
                    out[(size_t)r1 * N_NODES + cc] = acc[mt][nt][2];
            }
        }
    }

    // mirror tile via smem transpose -> coalesced float4 row writes
    if (!diag) {
        __syncthreads();
        float* stT = reinterpret_cast<float*>(sm);     // [128 cols][PT]
        int lr0 = wm * 64 + tr;
#pragma unroll
        for (int mt = 0; mt < 4; mt++) {
            int r0 = lr0 + mt * 16, r1 = r0 + 8;
#pragma unroll
            for (int nt = 0; nt < 4; nt++) {
                int lc = wn * 32 + nt * 8 + tc;
                stT[lc * PT + r0]       = acc[mt][nt][0];
                stT[(lc + 1) * PT + r0] = acc[mt][nt][1];
                stT[lc * PT + r1]       = acc[mt][nt][2];
                stT[(lc + 1) * PT + r1] = acc[mt][nt][3];
            }
        }
        __syncthreads();
        bool fullR = (rb + 128 <= N_NODES);
#pragma unroll
        for (int it = 0; it < 16; it++) {
            int j = wid + it * 8;
            int gr = cb + j;
            if (gr < N_NODES) {
                float4 v = *reinterpret_cast<const float4*>(stT + j * PT + lane * 4);
                float* p = out + (size_t)gr * N_NODES + rb + lane * 4;
                if (fullR) {
                    *reinterpret_cast<float4*>(p) = v;
                } else {
                    int c0 = rb + lane * 4;
                    if (c0 + 0 < N_NODES) p[0] = v.x;
                    if (c0 + 1 < N_NODES) p[1] = v.y;
                    if (c0 + 2 < N_NODES) p[2] = v.z;
                    if (c0 + 3 < N_NODES) p[3] = v.w;
                }
            }
        }
    }
}

// ---------------- launch ----------------
extern "C" void kernel_launch(void* const* d_in, const int* in_sizes, int n_in,
                              void* d_out, int out_size) {
    const float* x     = (const float*)d_in[0];
    const int*   ei    = (const int*)  d_in[1];
    const float* ew    = (const float*)d_in[2];
    const float* noise = (const float*)d_in[3];
    const float* W1    = (const float*)d_in[4];
    const float* b1    = (const float*)d_in[5];
    const float* W2    = (const float*)d_in[6];
    const float* b2    = (const float*)d_in[7];
    const float* W3    = (const float*)d_in[8];
    const float* b3    = (const float*)d_in[9];
    float* out = (float*)d_out;

    static int smem_set = 0;
    if (!smem_set) {
        cudaFuncSetAttribute(k_decoder, cudaFuncAttributeMaxDynamicSharedMemorySize, DEC_SMEM);
        smem_set = 1;
    }

    k_prep     <<<40, 256>>>();                            // 0
    k_deg_gemm1<<<938, 256>>>(ei, ew, x, W1);              // 1
    k_offsets  <<<40, 256>>>();                            // 2
    k_decoder  <<<dim3(1, 1), 256, DEC_SMEM>>>(out);       // 3  <- 1-CTA PROBE (profiled; overwritten)
    k_scatter  <<<625, 256>>>(ei, ew);                     // 4
    k_agg      <<<1250, 256>>>(1, b1, b2, b3, noise);      // 5
    k_gemm23   <<<313, 256>>>(W2, W3);                     // 6
    k_agg      <<<1250, 256>>>(2, b1, b2, b3, noise);      // 7
    dim3 g(NT, NT);
    k_decoder  <<<g, 256, DEC_SMEM>>>(out);                // 8
}